// round 15
// baseline (speedup 1.0000x reference)
#include <cuda_runtime.h>
#include <cuda_fp16.h>
#include <cstdint>

// out = x @ (W*mask)^T, block-diagonal mask: 5 blocks of 819 + single col 4095.
// R15: HMMA fp16 GEMM with IN-KERNEL x conversion (fp32 LDG -> cvt -> STS fp16
// in the mainloop's idle issue slots). Eliminates the convert_x pre-pass whose
// SM-time (~87us) was shown (R10/R14) to add almost linearly to wall time.
// BN=256 halves A-traffic per FLOP so the fp32 A path stays under the LTS cap.
// Single stream, 3 sequential launches: convert_w -> gemm -> last_col.

#define H     4096
#define BLKW  819
#define NBLK  5
#define KPAD  832          // 13 * 64 (W16 k-padding)
#define NPADW 1024         // 4 * 256 (W16 n-padding)
#define NCH   13
#define BK    64
#define BM    128
#define BN    256
#define NT    4            // n-tiles of 256 per block

#define TILE_A  16384      // A: 128 rows * 128B (fp16)
#define TILE_BB 32768      // B: 256 rows * 128B (fp16)
#define STAGE_B (TILE_A + TILE_BB)   // 49152
#define SMEM_B  (3 * STAGE_B)        // 147456

__device__ __align__(128) __half g_W16[(size_t)NBLK * NPADW * KPAD];

__device__ __forceinline__ uint32_t s2u(const void* p) {
    uint32_t a;
    asm("{ .reg .u64 t; cvta.to.shared.u64 t, %1; cvt.u32.u64 %0, t; }"
        : "=r"(a) : "l"(p));
    return a;
}
__device__ __forceinline__ void cp16(uint32_t s, const void* g) {
    asm volatile("cp.async.cg.shared.global [%0], [%1], 16;"
                 :: "r"(s), "l"(g) : "memory");
}
__device__ __forceinline__ void ldsm4(uint32_t& r0, uint32_t& r1,
                                      uint32_t& r2, uint32_t& r3, uint32_t a) {
    asm volatile("ldmatrix.sync.aligned.m8n8.x4.shared.b16 {%0,%1,%2,%3}, [%4];"
                 : "=r"(r0), "=r"(r1), "=r"(r2), "=r"(r3) : "r"(a));
}
__device__ __forceinline__ void mma16816(float* c, const uint32_t* a,
                                         uint32_t b0, uint32_t b1) {
    asm volatile(
        "mma.sync.aligned.m16n8k16.row.col.f32.f16.f16.f32 "
        "{%0,%1,%2,%3}, {%4,%5,%6,%7}, {%8,%9}, {%0,%1,%2,%3};"
        : "+f"(c[0]), "+f"(c[1]), "+f"(c[2]), "+f"(c[3])
        : "r"(a[0]), "r"(a[1]), "r"(a[2]), "r"(a[3]), "r"(b0), "r"(b1));
}

// ---------------- W: fp32 -> fp16 padded per-block layout (tiny, 5us) -------
__global__ void convert_w_kernel(const float* __restrict__ W) {
    const int b = blockIdx.y;
    const int t = blockIdx.x * blockDim.x + threadIdx.x;   // [0, NPADW*208)
    const int n  = t / (KPAD / 4);
    const int k4 = (t % (KPAD / 4)) * 4;
    const float* sp = W + (size_t)(b * BLKW + n) * H + b * BLKW + k4;
    float v[4];
    #pragma unroll
    for (int j = 0; j < 4; j++)
        v[j] = (n < BLKW && k4 + j < BLKW) ? sp[j] : 0.0f;
    __half2 h0 = __halves2half2(__float2half_rn(v[0]), __float2half_rn(v[1]));
    __half2 h1 = __halves2half2(__float2half_rn(v[2]), __float2half_rn(v[3]));
    const size_t dst = ((size_t)b * NPADW + n) * KPAD + k4;
    *(__half2*)(g_W16 + dst)     = h0;
    *(__half2*)(g_W16 + dst + 2) = h1;
}

// ---------------- fused GEMM: x loaded fp32, converted in-kernel ------------
__global__ void __launch_bounds__(512, 1)
gemm_kernel(float* __restrict__ out, const float* __restrict__ x, int M) {
    extern __shared__ __align__(1024) char smem[];
    const uint32_t sb = s2u(smem);
    const int tid = threadIdx.x;
    const int ntile = blockIdx.x;          // 0..3
    const int m0    = blockIdx.y * BM;
    const int blk   = blockIdx.z;

    const int w  = tid >> 5, l = tid & 31;
    const int wm = (w & 3) * 32;           // 4 m-warp rows
    const int wn = (w >> 2) * 64;          // 4 n-warp cols

    // ntile 3 covers cols 768..1023; only 768..818 valid -> only wn==0 active
    const bool active = (ntile < 3) || (wn == 0);

    // ---- A loader (fp32 x -> fp16 SMEM): row = tid>>2, quarter q = tid&3
    const int arow = tid >> 2;             // 0..127
    const int aq   = tid & 3;
    const float* gx = x + (size_t)(m0 + arow) * H + (size_t)blk * BLKW;
    const uint32_t asts = arow * 128;
    const uint32_t arx  = (arow & 7) << 4;

    float av[8];   // staging: one half (2 j-groups of 4 elems)

    // load half jh (j = jh*2, jh*2+1) of chunk at kc into av
    auto ldg_half = [&](int kc, int jh) {
        #pragma unroll
        for (int jj = 0; jj < 2; jj++) {
            const int j = jh * 2 + jj;
            const int c0 = aq * 4 + j * 16;
            if (kc + BK <= BLKW) {                       // fast path: all valid
                #pragma unroll
                for (int e = 0; e < 4; e++) av[jj * 4 + e] = gx[kc + c0 + e];
            } else {
                #pragma unroll
                for (int e = 0; e < 4; e++) {
                    const int kk = kc + c0 + e;
                    av[jj * 4 + e] = (kk < BLKW) ? gx[kk] : 0.0f;
                }
            }
        }
    };
    // convert av and store into stage st (absolute smem addr), half jh
    auto sts_half = [&](uint32_t st, int jh) {
        #pragma unroll
        for (int jj = 0; jj < 2; jj++) {
            const int j = jh * 2 + jj;
            __half2 h0 = __floats2half2_rn(av[jj * 4 + 0], av[jj * 4 + 1]);
            __half2 h1 = __floats2half2_rn(av[jj * 4 + 2], av[jj * 4 + 3]);
            uint2 u;
            u.x = *(uint32_t*)&h0;
            u.y = *(uint32_t*)&h1;
            const uint32_t so = asts + (((uint32_t)(aq * 8 + j * 32)) ^ arx);
            *(uint2*)(smem + (st - sb) + so) = u;
        }
    };

    // ---- B loader (fp16 from g_W16 via cp.async): row = tid>>1
    const int brow = tid >> 1;             // 0..255
    const int bc0  = (tid & 1) * 4;
    const __half* gB = g_W16 + ((size_t)blk * NPADW + ntile * BN + brow) * KPAD;
    const uint32_t bsts = TILE_A + brow * 128;
    const uint32_t brx  = (brow & 7) << 4;
    auto cpB = [&](uint32_t st, int kc) {
        #pragma unroll
        for (int jj = 0; jj < 4; jj++) {
            const int ch = bc0 + jj;
            cp16(st + bsts + (((uint32_t)(ch << 4)) ^ brx), gB + kc + ch * 8);
        }
        asm volatile("cp.async.commit_group;" ::: "memory");
    };

    // ---- ldmatrix lane addressing (same swizzle as producer)
    uint32_t aBase[2], aXor[2];
    #pragma unroll
    for (int mt = 0; mt < 2; mt++) {
        const int ml = wm + mt * 16 + (l & 7) + ((l >> 3) & 1) * 8;
        aBase[mt] = ml * 128;
        aXor[mt]  = (ml & 7) << 4;
    }
    const uint32_t kA = ((l >> 4) & 1) << 4;

    uint32_t bBase[4], bXor[4];
    const int g = l >> 3;
    #pragma unroll
    for (int q = 0; q < 4; q++) {
        const int nl = wn + q * 16 + ((g >> 1) << 3) + (l & 7);
        bBase[q] = TILE_A + nl * 128;
        bXor[q]  = (nl & 7) << 4;
    }
    const uint32_t kB = (g & 1) << 4;

    float c[2][8][4];
    #pragma unroll
    for (int mt = 0; mt < 2; mt++)
        #pragma unroll
        for (int nt = 0; nt < 8; nt++)
            #pragma unroll
            for (int r = 0; r < 4; r++) c[mt][nt][r] = 0.0f;

    auto compute2 = [&](uint32_t st, int ksbase) {
        #pragma unroll
        for (int ks = 0; ks < 2; ks++) {
            const uint32_t kso = (ksbase + ks) * 32;
            uint32_t a[2][4];
            #pragma unroll
            for (int mt = 0; mt < 2; mt++)
                ldsm4(a[mt][0], a[mt][1], a[mt][2], a[mt][3],
                      st + aBase[mt] + ((kso + kA) ^ aXor[mt]));
            uint32_t b[4][4];
            #pragma unroll
            for (int q = 0; q < 4; q++)
                ldsm4(b[q][0], b[q][1], b[q][2], b[q][3],
                      st + bBase[q] + ((kso + kB) ^ bXor[q]));
            #pragma unroll
            for (int mt = 0; mt < 2; mt++)
                #pragma unroll
                for (int nt = 0; nt < 8; nt++) {
                    const int q = nt >> 1;
                    if (nt & 1) mma16816(c[mt][nt], a[mt], b[q][2], b[q][3]);
                    else        mma16816(c[mt][nt], a[mt], b[q][0], b[q][1]);
                }
        }
    };

    // ---- prologue: chunks 0,1 fully staged; chunk 2 half-1 in flight
    {
        const uint32_t s0 = sb, s1 = sb + STAGE_B;
        ldg_half(0, 0);  sts_half(s0, 0);
        ldg_half(0, 1);  sts_half(s0, 1);
        ldg_half(BK, 0); sts_half(s1, 0);
        ldg_half(BK, 1); sts_half(s1, 1);
        cpB(s0, 0);
        cpB(s1, BK);
        ldg_half(2 * BK, 0);    // chunk 2, half 1 (held in av)
    }

    for (int i = 0; i < NCH; i++) {
        asm volatile("cp.async.wait_group 1;" ::: "memory");
        __syncthreads();

        const uint32_t st  = sb + (i % 3) * STAGE_B;
        const int nx = i + 2;
        const uint32_t stn = sb + (nx % 3) * STAGE_B;

        if (active) compute2(st, 0);            // ks 0,1

        if (nx < NCH) {
            sts_half(stn, 0);                   // chunk nx half 1 (loaded earlier)
            ldg_half(nx * BK, 1);               // chunk nx half 2
        }

        if (active) compute2(st, 2);            // ks 2,3

        if (nx < NCH) {
            sts_half(stn, 1);
            cpB(stn, nx * BK);                  // commits one group
            if (nx + 1 < NCH) ldg_half((nx + 1) * BK, 0);
        } else {
            asm volatile("cp.async.commit_group;" ::: "memory");
        }
    }

    // ---- epilogue: scalar STG.32 (colb may be odd)
    const int lim  = BLKW - ntile * BN;
    const size_t colb = (size_t)blk * BLKW + ntile * BN;
    const int l2 = l >> 2, l3 = (l & 3) << 1;
    if (active) {
        #pragma unroll
        for (int mt = 0; mt < 2; mt++) {
            const int rbase = m0 + wm + mt * 16 + l2;
            float* o0 = out + (size_t)rbase * H + colb;
            float* o1 = o0 + (size_t)8 * H;
            #pragma unroll
            for (int nt = 0; nt < 8; nt++) {
                const int col = wn + nt * 8 + l3;
                if (col < lim) {
                    o0[col] = c[mt][nt][0];
                    o1[col] = c[mt][nt][2];
                }
                if (col + 1 < lim) {
                    o0[col + 1] = c[mt][nt][1];
                    o1[col + 1] = c[mt][nt][3];
                }
            }
        }
    }
}

__global__ void last_col_kernel(const float* __restrict__ x,
                                const float* __restrict__ W,
                                float* __restrict__ out, int M) {
    const int m = blockIdx.x * blockDim.x + threadIdx.x;
    if (m < M) {
        const float w = __ldg(&W[(size_t)4095 * H + 4095]);
        out[(size_t)m * H + 4095] = x[(size_t)m * H + 4095] * w;
    }
}

extern "C" void kernel_launch(void* const* d_in, const int* in_sizes, int n_in,
                              void* d_out, int out_size) {
    const float* x = (const float*)d_in[0];
    const float* W = (const float*)d_in[1];
    float* out = (float*)d_out;
    const int M = in_sizes[0] / H;   // 16384

    cudaFuncSetAttribute(gemm_kernel,
                         cudaFuncAttributeMaxDynamicSharedMemorySize, SMEM_B);

    convert_w_kernel<<<dim3((NPADW * (KPAD / 4)) / 256, NBLK), 256>>>(W);

    dim3 grid(NT, M / BM, NBLK);
    gemm_kernel<<<grid, 512, SMEM_B>>>(out, x, M);

    last_col_kernel<<<(M + 255) / 256, 256>>>(x, W, out, M);
}